// round 9
// baseline (speedup 1.0000x reference)
#include <cuda_runtime.h>

// result = 2 * sum((img1-img2)^2) / n   (derivation: row-mean and col-mean sums
// each equal total/(B*C*W) when H==W, so acc/W = 2*total/n)
//
// Champion structure (R8, 12.768us): plain default-policy float4 loads,
// dynamic grid-stride loop, one full wave (2048 thr/SM), single graph node
// with in-kernel arrival-counter finish. This round's only change: block
// shape 256x8 -> 512x4 per SM (same thread count, half the blocks/atomics).

__device__ float        g_acc   = 0.0f;
__device__ unsigned int g_count = 0;

__global__ void __launch_bounds__(512) reduce_kernel(
    const float4* __restrict__ a,
    const float4* __restrict__ b,
    float* __restrict__ out,
    int n4,
    float scale)
{
    float sum = 0.0f;
    int idx = blockIdx.x * blockDim.x + threadIdx.x;
    int stride = gridDim.x * blockDim.x;

    for (int i = idx; i < n4; i += stride) {
        float4 x = a[i];
        float4 y = b[i];
        float d0 = x.x - y.x;
        float d1 = x.y - y.y;
        float d2 = x.z - y.z;
        float d3 = x.w - y.w;
        sum += d0 * d0 + d1 * d1 + d2 * d2 + d3 * d3;
    }

    // warp reduction
    #pragma unroll
    for (int off = 16; off > 0; off >>= 1)
        sum += __shfl_down_sync(0xFFFFFFFFu, sum, off);

    __shared__ float warp_sums[16];
    int lane = threadIdx.x & 31;
    int wid  = threadIdx.x >> 5;
    if (lane == 0) warp_sums[wid] = sum;
    __syncthreads();

    if (wid == 0) {
        sum = (lane < (blockDim.x >> 5)) ? warp_sums[lane] : 0.0f;
        #pragma unroll
        for (int off = 8; off > 0; off >>= 1)
            sum += __shfl_down_sync(0xFFFFFFFFu, sum, off);
        if (lane == 0) {
            atomicAdd(&g_acc, sum);
            __threadfence();
            unsigned int old = atomicAdd(&g_count, 1u);
            if (old == gridDim.x - 1) {
                // Last block: publish and reset for the next (replay) call.
                out[0] = g_acc * scale;
                g_acc = 0.0f;
                __threadfence();
                g_count = 0;
            }
        }
    }
}

extern "C" void kernel_launch(void* const* d_in, const int* in_sizes, int n_in,
                              void* d_out, int out_size)
{
    const float4* a = (const float4*)d_in[0];
    const float4* b = (const float4*)d_in[1];
    float* out = (float*)d_out;

    int n  = in_sizes[0];          // 16*3*512*512 = 12,582,912 (divisible by 4)
    int n4 = n >> 2;
    float scale = 2.0f / (float)n;

    const int threads = 512;
    const int blocks  = 148 * 4;   // one full wave: 4 CTAs/SM x 512 = 2048 thr/SM
    reduce_kernel<<<blocks, threads>>>(a, b, out, n4, scale);
}